// round 2
// baseline (speedup 1.0000x reference)
#include <cuda_runtime.h>
#include <math.h>

// Problem constants
#define B_  2
#define T_  512
#define D_  512
#define NTOK (B_ * T_)          // 1024
#define NTOT (B_ * T_ * D_)     // 524288
#define THREADS 256
#define NWARP (THREADS / 32)

// Global accumulator for ||res||^2 (double for safe accumulation)
__device__ double g_sumsq;

__global__ void zero_acc_kernel() { g_sumsq = 0.0; }

// Extended Golay (24,12) generator, analytic form:
//  G[k][l] = (l<12)      ? (l==k)
//          : (l<23)      ? ((k + (l-12)) % 2)
//          :               (k % 2)          // row parity of first 23 cols

__global__ __launch_bounds__(THREADS) void token_kernel(
    const int*   __restrict__ token_ids,   // [NTOK]
    const float* __restrict__ resonances,  // [D]
    const float* __restrict__ emb_scales,  // [D]
    const float* __restrict__ emb_shifts,  // [D]
    const float* __restrict__ emb_norm_p,  // [1]
    const float* __restrict__ W_enc,       // [D,24] row-major
    const float* __restrict__ b_enc,       // [24]
    const float* __restrict__ W_dec,       // [24,D] row-major
    const float* __restrict__ b_dec,       // [D]
    const float* __restrict__ ecc_p,       // [1]
    const float* __restrict__ ep_p,        // [1]
    float*       __restrict__ out)         // [NTOK, D]
{
    __shared__ float s_emb[D_];
    __shared__ float s_red[NWARP];
    __shared__ float s_proj[24];
    __shared__ float s_latt[12];
    __shared__ float s_corr[24];
    __shared__ float s_scalar[2];

    const int bt   = blockIdx.x;       // flat token index b*T + t
    const int t    = bt % T_;
    const int tid  = threadIdx.x;
    const int lane = tid & 31;
    const int wid  = tid >> 5;

    const float ecc = ecc_p[0];
    const float ep  = ep_p[0];

    // ---------- Phase A: embedding + token norm ----------
    const float tv   = (float)(token_ids[bt] % 1000000) * 1e-6f;
    const float base = tv + (float)t;

    float sumsq = 0.f;
    #pragma unroll
    for (int r = 0; r < 2; r++) {
        const int d = tid + r * THREADS;
        float sn, c;
        sincosf(resonances[d] * base, &sn, &c);
        const float comp = c * (1.f + sn) + sn * sn;
        const float e    = comp * emb_scales[d] + emb_shifts[d];
        s_emb[d] = e;
        sumsq += e * e;
    }
    #pragma unroll
    for (int o = 16; o; o >>= 1) sumsq += __shfl_xor_sync(0xffffffffu, sumsq, o);
    if (lane == 0) s_red[wid] = sumsq;
    __syncthreads();
    if (tid < 32) {
        float v = (lane < NWARP) ? s_red[lane] : 0.f;
        #pragma unroll
        for (int o = 4; o; o >>= 1) v += __shfl_xor_sync(0xffffffffu, v, o);
        if (lane == 0) s_scalar[0] = sqrtf(v);
    }
    __syncthreads();
    const float tok_norm = s_scalar[0];
    const float emb_norm = emb_norm_p[0];
    const float f    = (tok_norm > 0.f) ? (emb_norm / tok_norm) : 1.f;
    const float e_in = (tok_norm > 0.f) ? emb_norm : tok_norm;   // == ||normalized emb||

    #pragma unroll
    for (int r = 0; r < 2; r++) { const int d = tid + r * THREADS; s_emb[d] *= f; }
    __syncthreads();

    // ---------- Phase B: proj = emb @ W_enc + b_enc  (warp per column) ----------
    for (int l = wid; l < 24; l += NWARP) {
        float acc = 0.f;
        #pragma unroll
        for (int j = 0; j < D_ / 32; j++) {
            const int d = lane + 32 * j;
            acc += s_emb[d] * W_enc[d * 24 + l];
        }
        #pragma unroll
        for (int o = 16; o; o >>= 1) acc += __shfl_xor_sync(0xffffffffu, acc, o);
        if (lane == 0) s_proj[l] = acc + b_enc[l];
    }
    __syncthreads();

    // ---------- Phase B2: Golay encode/quantize/rescale + decode/threshold (warp 0) ----------
    if (wid == 0) {
        float latt = 0.f;
        if (lane < 12) {
            float ge = s_proj[lane];                       // identity columns
            #pragma unroll
            for (int j = 0; j < 11; j++)
                if ((lane + j) & 1) ge += s_proj[12 + j];  // parity columns
            if (lane & 1) ge += s_proj[23];                // overall-parity column
            latt = rintf(ge / ecc) * ecc;                  // round-half-even, matches jnp.round
        }
        float ls = latt * latt;
        #pragma unroll
        for (int o = 16; o; o >>= 1) ls += __shfl_xor_sync(0xffffffffu, ls, o);
        const float e_out = sqrtf(ls);
        latt = latt * (e_in / (e_out + 1e-8f)) * ep;

        float ls2 = latt * latt;
        #pragma unroll
        for (int o = 16; o; o >>= 1) ls2 += __shfl_xor_sync(0xffffffffu, ls2, o);
        const float e_in2 = sqrtf(ls2);

        if (lane < 12) s_latt[lane] = latt;
        __syncwarp();

        if (lane < 24) {
            float gd;
            if (lane < 12) {
                gd = s_latt[lane];
            } else if (lane < 23) {
                const int j = lane - 12;
                gd = 0.f;
                #pragma unroll
                for (int k = 0; k < 12; k++)
                    if ((k + j) & 1) gd += s_latt[k];
            } else {
                gd = s_latt[1] + s_latt[3] + s_latt[5] + s_latt[7] + s_latt[9] + s_latt[11];
            }
            s_corr[lane] = (fabsf(gd) > ecc) ? gd : 0.f;
        }
        if (lane == 0) s_scalar[1] = e_in2;
    }
    __syncthreads();

    // ---------- Phase C: res = corrected @ W_dec + b_dec, rescale, write, norm ----------
    const float e_in2 = s_scalar[1];
    float acc[2];
    float psum = 0.f;
    #pragma unroll
    for (int r = 0; r < 2; r++) {
        const int d = tid + r * THREADS;
        float a = b_dec[d];
        #pragma unroll
        for (int l = 0; l < 24; l++) a += s_corr[l] * W_dec[l * D_ + d];
        acc[r] = a;
        psum += a * a;
    }
    #pragma unroll
    for (int o = 16; o; o >>= 1) psum += __shfl_xor_sync(0xffffffffu, psum, o);
    if (lane == 0) s_red[wid] = psum;
    __syncthreads();
    if (tid < 32) {
        float v = (lane < NWARP) ? s_red[lane] : 0.f;
        #pragma unroll
        for (int o = 4; o; o >>= 1) v += __shfl_xor_sync(0xffffffffu, v, o);
        if (lane == 0) s_scalar[0] = v;   // e_out2^2
    }
    __syncthreads();
    const float e_out2sq = s_scalar[0];
    const float e_out2   = sqrtf(e_out2sq);
    const float scale    = e_in2 / (e_out2 + 1e-8f) * ep;

    #pragma unroll
    for (int r = 0; r < 2; r++) {
        const int d = tid + r * THREADS;
        out[bt * D_ + d] = acc[r] * scale;
    }

    // global ||res||^2 contribution: scale^2 * sum(raw^2)
    if (tid == 0) atomicAdd(&g_sumsq, (double)scale * (double)scale * (double)e_out2sq);
}

// out *= frac_norm * ||res||   (fd cancels out of the reference exactly)
__global__ __launch_bounds__(THREADS) void scale_kernel(
    float* __restrict__ out, const float* __restrict__ frac_norm_p)
{
    const int i = blockIdx.x * blockDim.x + threadIdx.x;
    if (i < NTOT) {
        const float m = frac_norm_p[0] * (float)sqrt(g_sumsq);
        out[i] *= m;
    }
}

extern "C" void kernel_launch(void* const* d_in, const int* in_sizes, int n_in,
                              void* d_out, int out_size)
{
    (void)in_sizes; (void)n_in; (void)out_size;
    const int*   token_ids  = (const int*)  d_in[0];
    const float* resonances = (const float*)d_in[1];
    const float* emb_scales = (const float*)d_in[2];
    const float* emb_shifts = (const float*)d_in[3];
    const float* emb_norm   = (const float*)d_in[4];
    // d_in[5] scale_weights, d_in[6] fractal_bias: provably cancel out
    const float* frac_norm  = (const float*)d_in[7];
    const float* W_enc      = (const float*)d_in[8];
    const float* b_enc      = (const float*)d_in[9];
    const float* W_dec      = (const float*)d_in[10];
    const float* b_dec      = (const float*)d_in[11];
    const float* ecc        = (const float*)d_in[12];
    const float* ep         = (const float*)d_in[13];
    float* out = (float*)d_out;

    zero_acc_kernel<<<1, 1>>>();
    token_kernel<<<NTOK, THREADS>>>(token_ids, resonances, emb_scales, emb_shifts,
                                    emb_norm, W_enc, b_enc, W_dec, b_dec,
                                    ecc, ep, out);
    scale_kernel<<<(NTOT + THREADS - 1) / THREADS, THREADS>>>(out, frac_norm);
}

// round 3
// speedup vs baseline: 1.4885x; 1.4885x over previous
#include <cuda_runtime.h>
#include <math.h>

#define B_  2
#define T_  512
#define D_  512
#define NTOK (B_ * T_)          // 1024
#define NTOT (B_ * T_ * D_)     // 524288
#define K1_THREADS 256
#define NWARP (K1_THREADS / 32) // 8

// ---- device scratch (no allocations allowed) ----
__device__ float  g_WencT[24 * D_];   // W_enc transposed: [24][512]
__device__ float  g_gram [24 * 24];   // W_dec @ W_dec^T
__device__ float  g_wb   [24];        // W_dec @ b_dec
__device__ float  g_bb;               // ||b_dec||^2
__device__ double g_sumsq;            // global ||res||^2
__device__ float  g_corr [NTOK * 24]; // per-token corrected Golay vector
__device__ float  g_scale[NTOK];      // per-token output scale

// Fast sincos: Cody-Waite 2-term range reduction + MUFU. |x| <= ~26000.
// y error ~2e-7 abs; __sinf/__cosf on [-pi,pi] ~4e-7 abs.
__device__ __forceinline__ void fast_sincos(float x, float* s, float* c) {
    const float INV2PI = 0.15915494309189535f;
    float k = rintf(x * INV2PI);
    float y = fmaf(k, -6.2831855f, x);      // H (float 2pi, slightly high)
    y = fmaf(k, 1.7484556e-7f, y);          // correct H back to true 2pi
    *s = __sinf(y);
    *c = __cosf(y);
}

// ---------------- Kernel P: prep (25 blocks x 256) ----------------
// blocks 0..23: Gram row i + wb[i].  block 24: transpose W_enc, bb, zero g_sumsq.
__global__ __launch_bounds__(256) void prep_kernel(
    const float* __restrict__ W_enc,   // [512,24]
    const float* __restrict__ W_dec,   // [24,512]
    const float* __restrict__ b_dec)   // [512]
{
    const int tid  = threadIdx.x;
    const int lane = tid & 31;
    const int wid  = tid >> 5;
    const int i    = blockIdx.x;

    if (i < 24) {
        // each warp computes 3 Gram entries of row i; warp 0 also wb[i]
        #pragma unroll
        for (int cidx = 0; cidx < 3; cidx++) {
            const int j = wid + 8 * cidx;
            float acc = 0.f;
            #pragma unroll
            for (int m = 0; m < D_ / 32; m++) {
                const int d = lane + 32 * m;
                acc += W_dec[i * D_ + d] * W_dec[j * D_ + d];
            }
            #pragma unroll
            for (int o = 16; o; o >>= 1) acc += __shfl_xor_sync(0xffffffffu, acc, o);
            if (lane == 0) g_gram[i * 24 + j] = acc;
        }
        if (wid == 0) {
            float acc = 0.f;
            #pragma unroll
            for (int m = 0; m < D_ / 32; m++) {
                const int d = lane + 32 * m;
                acc += W_dec[i * D_ + d] * b_dec[d];
            }
            #pragma unroll
            for (int o = 16; o; o >>= 1) acc += __shfl_xor_sync(0xffffffffu, acc, o);
            if (lane == 0) g_wb[i] = acc;
        }
    } else {
        // transpose W_enc (coalesced read, scattered write; one-time, tiny)
        for (int idx = tid; idx < D_ * 24; idx += 256) {
            const int d = idx / 24;
            const int l = idx - d * 24;
            g_WencT[l * D_ + d] = W_enc[idx];
        }
        // bb = ||b_dec||^2
        __shared__ float s_red[8];
        float p = b_dec[tid] * b_dec[tid] + b_dec[tid + 256] * b_dec[tid + 256];
        #pragma unroll
        for (int o = 16; o; o >>= 1) p += __shfl_xor_sync(0xffffffffu, p, o);
        if (lane == 0) s_red[wid] = p;
        __syncthreads();
        if (tid == 0) {
            float v = 0.f;
            #pragma unroll
            for (int w = 0; w < 8; w++) v += s_red[w];
            g_bb = v;
            g_sumsq = 0.0;
        }
    }
}

// ---------------- Kernel 1: per-token scalars (1024 blocks x 256) ----------------
__global__ __launch_bounds__(K1_THREADS) void token_kernel(
    const int*   __restrict__ token_ids,
    const float* __restrict__ resonances,
    const float* __restrict__ emb_scales,
    const float* __restrict__ emb_shifts,
    const float* __restrict__ emb_norm_p,
    const float* __restrict__ b_enc,
    const float* __restrict__ ecc_p,
    const float* __restrict__ ep_p)
{
    __shared__ float s_emb[D_];
    __shared__ float s_red[NWARP];
    __shared__ float s_proj[24];
    __shared__ float s_latt[12];
    __shared__ float s_scalar[1];

    const int bt   = blockIdx.x;
    const int t    = bt & (T_ - 1);
    const int tid  = threadIdx.x;
    const int lane = tid & 31;
    const int wid  = tid >> 5;

    const float ecc = ecc_p[0];
    const float ep  = ep_p[0];

    // ---- Phase A: raw embedding + token norm (fold normalize into matvec) ----
    const float tv   = (float)(token_ids[bt] % 1000000) * 1e-6f;
    const float base = tv + (float)t;

    float sumsq = 0.f;
    #pragma unroll
    for (int r = 0; r < 2; r++) {
        const int d = tid + r * K1_THREADS;
        float sn, c;
        fast_sincos(resonances[d] * base, &sn, &c);
        const float comp = c * (1.f + sn) + sn * sn;
        const float e    = comp * emb_scales[d] + emb_shifts[d];
        s_emb[d] = e;
        sumsq += e * e;
    }
    #pragma unroll
    for (int o = 16; o; o >>= 1) sumsq += __shfl_xor_sync(0xffffffffu, sumsq, o);
    if (lane == 0) s_red[wid] = sumsq;
    __syncthreads();
    if (tid == 0) {
        float v = 0.f;
        #pragma unroll
        for (int w = 0; w < NWARP; w++) v += s_red[w];
        s_scalar[0] = sqrtf(v);
    }
    __syncthreads();
    const float tok_norm = s_scalar[0];
    const float emb_norm = emb_norm_p[0];
    const float f    = (tok_norm > 0.f) ? (emb_norm / tok_norm) : 1.f;
    const float e_in = (tok_norm > 0.f) ? emb_norm : tok_norm;

    // ---- Phase B: proj = f*(emb_raw @ W_enc) + b_enc  (coalesced W_encT) ----
    #pragma unroll
    for (int cidx = 0; cidx < 3; cidx++) {
        const int l = wid + 8 * cidx;
        float acc = 0.f;
        #pragma unroll
        for (int m = 0; m < D_ / 32; m++) {
            const int d = lane + 32 * m;
            acc += s_emb[d] * g_WencT[l * D_ + d];
        }
        #pragma unroll
        for (int o = 16; o; o >>= 1) acc += __shfl_xor_sync(0xffffffffu, acc, o);
        if (lane == 0) s_proj[l] = fmaf(f, acc, b_enc[l]);
    }
    __syncthreads();

    // ---- Phase B2: Golay encode/quantize/rescale + decode/threshold (warp 0) ----
    if (wid == 0) {
        float latt = 0.f;
        if (lane < 12) {
            float ge = s_proj[lane];
            #pragma unroll
            for (int j = 0; j < 11; j++)
                if ((lane + j) & 1) ge += s_proj[12 + j];
            if (lane & 1) ge += s_proj[23];
            latt = rintf(ge / ecc) * ecc;
        }
        float ls = latt * latt;
        #pragma unroll
        for (int o = 16; o; o >>= 1) ls += __shfl_xor_sync(0xffffffffu, ls, o);
        const float e_out = sqrtf(ls);
        const float lscale = (e_in / (e_out + 1e-8f)) * ep;
        latt *= lscale;
        const float e_in2 = e_out * lscale;   // == ||latt_scaled||

        if (lane < 12) s_latt[lane] = latt;
        __syncwarp();

        float corr = 0.f;
        if (lane < 24) {
            float gd;
            if (lane < 12) {
                gd = s_latt[lane];
            } else if (lane < 23) {
                const int j = lane - 12;
                gd = 0.f;
                #pragma unroll
                for (int k = 0; k < 12; k++)
                    if ((k + j) & 1) gd += s_latt[k];
            } else {
                gd = s_latt[1] + s_latt[3] + s_latt[5] + s_latt[7] + s_latt[9] + s_latt[11];
            }
            corr = (fabsf(gd) > ecc) ? gd : 0.f;
            g_corr[bt * 24 + lane] = corr;
            s_latt[0] = s_latt[0]; // no-op keep
        }
        // stash corr for quadratic form via shared (reuse s_proj)
        if (lane < 24) s_proj[lane] = corr;
        __syncwarp();

        // ||corr @ W_dec + b||^2 = c^T G c + 2 c^T wb + bb
        float r = 0.f;
        if (lane < 24) {
            float dotG = 0.f;
            #pragma unroll
            for (int j = 0; j < 24; j++)
                dotG += g_gram[lane * 24 + j] * s_proj[j];
            r = s_proj[lane] * dotG + 2.f * s_proj[lane] * g_wb[lane];
        }
        #pragma unroll
        for (int o = 16; o; o >>= 1) r += __shfl_xor_sync(0xffffffffu, r, o);
        if (lane == 0) {
            const float e2sq  = r + g_bb;
            const float e_out2 = sqrtf(fmaxf(e2sq, 0.f));
            const float scale  = e_in2 / (e_out2 + 1e-8f) * ep;
            g_scale[bt] = scale;
            const double tn = (double)(scale * e_out2);
            atomicAdd(&g_sumsq, tn * tn);
        }
    }
}

// ---------------- Kernel 2: output (1024 blocks x 512) ----------------
// out[bt,d] = (corr @ W_dec + b_dec)[d] * scale_bt * frac_norm * ||res||
__global__ __launch_bounds__(512) void out_kernel(
    const float* __restrict__ W_dec,      // [24,512]
    const float* __restrict__ b_dec,      // [512]
    const float* __restrict__ frac_norm_p,
    float*       __restrict__ out)
{
    __shared__ float s_c[24];
    __shared__ float s_mul[1];

    const int bt  = blockIdx.x;
    const int tid = threadIdx.x;

    if (tid < 24) s_c[tid] = g_corr[bt * 24 + tid];
    if (tid == 31) {
        const float m = frac_norm_p[0] * (float)sqrt(g_sumsq);
        s_mul[0] = g_scale[bt] * m;
    }
    __syncthreads();

    float acc = b_dec[tid];
    #pragma unroll
    for (int l = 0; l < 24; l++)
        acc = fmaf(s_c[l], W_dec[l * D_ + tid], acc);
    out[bt * D_ + tid] = acc * s_mul[0];
}

extern "C" void kernel_launch(void* const* d_in, const int* in_sizes, int n_in,
                              void* d_out, int out_size)
{
    (void)in_sizes; (void)n_in; (void)out_size;
    const int*   token_ids  = (const int*)  d_in[0];
    const float* resonances = (const float*)d_in[1];
    const float* emb_scales = (const float*)d_in[2];
    const float* emb_shifts = (const float*)d_in[3];
    const float* emb_norm   = (const float*)d_in[4];
    // d_in[5] scale_weights, d_in[6] fractal_bias: provably cancel out of the output
    const float* frac_norm  = (const float*)d_in[7];
    const float* W_enc      = (const float*)d_in[8];
    const float* b_enc      = (const float*)d_in[9];
    const float* W_dec      = (const float*)d_in[10];
    const float* b_dec      = (const float*)d_in[11];
    const float* ecc        = (const float*)d_in[12];
    const float* ep         = (const float*)d_in[13];
    float* out = (float*)d_out;

    prep_kernel<<<25, 256>>>(W_enc, W_dec, b_dec);
    token_kernel<<<NTOK, K1_THREADS>>>(token_ids, resonances, emb_scales, emb_shifts,
                                       emb_norm, b_enc, ecc, ep);
    out_kernel<<<NTOK, 512>>>(W_dec, b_dec, frac_norm, out);
}

// round 4
// speedup vs baseline: 1.7549x; 1.1789x over previous
#include <cuda_runtime.h>
#include <math.h>

#define B_   2
#define T_   512
#define D_   512
#define NTOK (B_ * T_)       // 1024
#define NBLK 148             // one CTA per SM -> residency guaranteed
#define TPB  512
#define KMAX 7               // ceil(NTOK / NBLK)
#define WT_PITCH 513         // padded pitch for transposed W_enc (bank-conflict-free)

// dynamic smem layout: [24*513] W_encT | [24*512] W_dec | [KMAX*512] emb/res
#define SMEM_BYTES ((24 * WT_PITCH + 24 * D_ + KMAX * D_) * (int)sizeof(float))

__device__ double   g_blocksum[NBLK];
__device__ unsigned g_bar_cnt;   // zero-initialized; reset by last arriver
__device__ unsigned g_bar_gen;   // monotonically increasing across replays

// Fast sincos: Cody-Waite 2-term range reduction + MUFU (|x| small here)
__device__ __forceinline__ void fast_sincos(float x, float* s, float* c) {
    const float INV2PI = 0.15915494309189535f;
    float k = rintf(x * INV2PI);
    float y = fmaf(k, -6.2831855f, x);
    y = fmaf(k, 1.7484556e-7f, y);
    *s = __sinf(y);
    *c = __cosf(y);
}

__device__ __forceinline__ void grid_barrier() {
    __syncthreads();
    if (threadIdx.x == 0) {
        __threadfence();
        unsigned gen = *(volatile unsigned*)&g_bar_gen;
        if (atomicAdd(&g_bar_cnt, 1u) == NBLK - 1) {
            g_bar_cnt = 0;                    // reset for next replay
            __threadfence();
            *(volatile unsigned*)&g_bar_gen = gen + 1;   // release
        } else {
            while (*(volatile unsigned*)&g_bar_gen == gen) { __nanosleep(32); }
        }
        __threadfence();
    }
    __syncthreads();
}

extern __shared__ float s_dyn[];

__global__ __launch_bounds__(TPB, 1) void fused_kernel(
    const int*   __restrict__ token_ids,
    const float* __restrict__ resonances,
    const float* __restrict__ emb_scales,
    const float* __restrict__ emb_shifts,
    const float* __restrict__ emb_norm_p,
    const float* __restrict__ frac_norm_p,
    const float* __restrict__ W_enc,      // [512,24]
    const float* __restrict__ b_enc,      // [24]
    const float* __restrict__ W_dec,      // [24,512]
    const float* __restrict__ b_dec,      // [512]
    const float* __restrict__ ecc_p,
    const float* __restrict__ ep_p,
    float*       __restrict__ out)        // [1024,512]
{
    float* s_wT  = s_dyn;                       // [24][513] W_enc^T, padded
    float* s_wd  = s_dyn + 24 * WT_PITCH;       // [24][512] W_dec
    float* s_res = s_wd  + 24 * D_;             // [KMAX][512] emb, then res

    __shared__ float  s_redA[KMAX][16];
    __shared__ float  s_proj[KMAX][24];
    __shared__ float  s_latt[KMAX][12];
    __shared__ float  s_corr[KMAX][24];
    __shared__ float  s_f[KMAX], s_ein[KMAX], s_ein2[KMAX], s_scale[KMAX];
    __shared__ double s_contrib[KMAX];
    __shared__ float  s_mul;

    const int tid  = threadIdx.x;
    const int lane = tid & 31;
    const int wid  = tid >> 5;
    const int blk  = blockIdx.x;

    const int   nk       = (blk + (KMAX - 1) * NBLK < NTOK) ? KMAX : KMAX - 1;
    const float ecc      = ecc_p[0];
    const float ep       = ep_p[0];
    const float emb_norm = emb_norm_p[0];

    // ---- Phase 0: stage weights into smem (per block; reused for nk tokens) ----
    for (int idx = tid; idx < D_ * 24; idx += TPB) {
        const int d = idx / 24;
        const int l = idx - d * 24;
        s_wT[l * WT_PITCH + d] = W_enc[idx];
    }
    for (int idx = tid; idx < 24 * D_; idx += TPB)
        s_wd[idx] = W_dec[idx];

    // ---- Phase A: embeddings for all tokens of this block (d = tid) ----
    const float res_d = resonances[tid];
    const float esc_d = emb_scales[tid];
    const float esh_d = emb_shifts[tid];
    #pragma unroll
    for (int k = 0; k < KMAX; k++) {
        const int bt = blk + k * NBLK;
        if (bt < NTOK) {
            const float tv   = (float)(token_ids[bt] % 1000000) * 1e-6f;
            const float base = tv + (float)(bt & (T_ - 1));
            float sn, c;
            fast_sincos(res_d * base, &sn, &c);
            const float e = fmaf(c * (1.f + sn) + sn * sn, esc_d, esh_d);
            s_res[k * D_ + tid] = e;
            float p = e * e;
            #pragma unroll
            for (int o = 16; o; o >>= 1) p += __shfl_xor_sync(0xffffffffu, p, o);
            if (lane == 0) s_redA[k][wid] = p;
        }
    }
    __syncthreads();
    if (wid < KMAX) {
        const int k = wid;
        if (blk + k * NBLK < NTOK) {
            float v = (lane < 16) ? s_redA[k][lane] : 0.f;
            #pragma unroll
            for (int o = 8; o; o >>= 1) v += __shfl_xor_sync(0xffffffffu, v, o);
            if (lane == 0) {
                const float tn = sqrtf(v);
                s_f[k]   = (tn > 0.f) ? (emb_norm / tn) : 1.f;
                s_ein[k] = (tn > 0.f) ? emb_norm : tn;
            }
        }
    }
    __syncthreads();

    // ---- Phase B: proj[k][l] = f_k * (emb_k . WencT_l) + b_enc[l] ----
    const int ncol = nk * 24;
    for (int c = wid; c < ncol; c += 16) {
        const int k = c / 24;
        const int l = c - k * 24;
        float acc = 0.f;
        #pragma unroll
        for (int j = 0; j < D_ / 32; j++) {
            const int d = lane + 32 * j;
            acc = fmaf(s_res[k * D_ + d], s_wT[l * WT_PITCH + d], acc);
        }
        #pragma unroll
        for (int o = 16; o; o >>= 1) acc += __shfl_xor_sync(0xffffffffu, acc, o);
        if (lane == 0) s_proj[k][l] = fmaf(s_f[k], acc, b_enc[l]);
    }
    __syncthreads();

    // ---- Phase B2: Golay encode/quantize/rescale/decode/threshold, warp k = token k ----
    if (wid < nk) {
        const int k = wid;
        float latt = 0.f;
        if (lane < 12) {
            float ge = s_proj[k][lane];
            #pragma unroll
            for (int j = 0; j < 11; j++)
                if ((lane + j) & 1) ge += s_proj[k][12 + j];
            if (lane & 1) ge += s_proj[k][23];
            latt = rintf(ge / ecc) * ecc;
        }
        float ls = latt * latt;
        #pragma unroll
        for (int o = 16; o; o >>= 1) ls += __shfl_xor_sync(0xffffffffu, ls, o);
        const float e_out  = sqrtf(ls);
        const float lscale = (s_ein[k] / (e_out + 1e-8f)) * ep;
        latt *= lscale;
        if (lane < 12) s_latt[k][lane] = latt;
        __syncwarp();
        if (lane < 24) {
            float gd;
            if (lane < 12) {
                gd = s_latt[k][lane];
            } else if (lane < 23) {
                const int j = lane - 12;
                gd = 0.f;
                #pragma unroll
                for (int kk = 0; kk < 12; kk++)
                    if ((kk + j) & 1) gd += s_latt[k][kk];
            } else {
                gd = s_latt[k][1] + s_latt[k][3] + s_latt[k][5] + s_latt[k][7]
                   + s_latt[k][9] + s_latt[k][11];
            }
            s_corr[k][lane] = (fabsf(gd) > ecc) ? gd : 0.f;
        }
        if (lane == 0) s_ein2[k] = e_out * lscale;   // ||latt_scaled||
    }
    __syncthreads();

    // ---- Phase C: dec matvec for all tokens (d = tid), raw norms ----
    float acc[KMAX];
    const float bd = b_dec[tid];
    #pragma unroll
    for (int k = 0; k < KMAX; k++) acc[k] = bd;
    #pragma unroll
    for (int l = 0; l < 24; l++) {
        const float wl = s_wd[l * D_ + tid];
        #pragma unroll
        for (int k = 0; k < KMAX; k++)
            acc[k] = fmaf(s_corr[k][l], wl, acc[k]);
    }
    #pragma unroll
    for (int k = 0; k < KMAX; k++) {
        float p = acc[k] * acc[k];
        #pragma unroll
        for (int o = 16; o; o >>= 1) p += __shfl_xor_sync(0xffffffffu, p, o);
        if (lane == 0) s_redA[k][wid] = p;
    }
    __syncthreads();
    if (wid < KMAX) {
        const int k = wid;
        float v = (lane < 16) ? s_redA[k][lane] : 0.f;
        #pragma unroll
        for (int o = 8; o; o >>= 1) v += __shfl_xor_sync(0xffffffffu, v, o);
        if (lane == 0) {
            if (k < nk) {
                const float e2 = sqrtf(fmaxf(v, 0.f));
                const float sc = s_ein2[k] / (e2 + 1e-8f) * ep;
                s_scale[k] = sc;
                const double tn = (double)(sc * e2);
                s_contrib[k] = tn * tn;
            } else {
                s_contrib[k] = 0.0;
            }
        }
    }
    __syncthreads();

    #pragma unroll
    for (int k = 0; k < KMAX; k++)
        if (k < nk) s_res[k * D_ + tid] = acc[k] * s_scale[k];
    if (tid == 0) {
        double s = 0.0;
        #pragma unroll
        for (int k = 0; k < KMAX; k++) s += s_contrib[k];
        g_blocksum[blk] = s;
    }

    // ---- Grid barrier: all 148 resident CTAs ----
    grid_barrier();

    // ---- Global norm (deterministic fixed-order reduce), fused output write ----
    if (wid == 0) {
        double s = 0.0;
        for (int i = lane; i < NBLK; i += 32) s += __ldcg(&g_blocksum[i]);
        #pragma unroll
        for (int o = 16; o; o >>= 1) s += __shfl_xor_sync(0xffffffffu, s, o);
        if (lane == 0) s_mul = frac_norm_p[0] * (float)sqrt(s);
    }
    __syncthreads();
    const float m = s_mul;
    #pragma unroll
    for (int k = 0; k < KMAX; k++) {
        const int bt = blk + k * NBLK;
        if (bt < NTOK) out[bt * D_ + tid] = s_res[k * D_ + tid] * m;
    }
}

extern "C" void kernel_launch(void* const* d_in, const int* in_sizes, int n_in,
                              void* d_out, int out_size)
{
    (void)in_sizes; (void)n_in; (void)out_size;
    const int*   token_ids  = (const int*)  d_in[0];
    const float* resonances = (const float*)d_in[1];
    const float* emb_scales = (const float*)d_in[2];
    const float* emb_shifts = (const float*)d_in[3];
    const float* emb_norm   = (const float*)d_in[4];
    // d_in[5] scale_weights, d_in[6] fractal_bias: cancel out of the output exactly
    const float* frac_norm  = (const float*)d_in[7];
    const float* W_enc      = (const float*)d_in[8];
    const float* b_enc      = (const float*)d_in[9];
    const float* W_dec      = (const float*)d_in[10];
    const float* b_dec      = (const float*)d_in[11];
    const float* ecc        = (const float*)d_in[12];
    const float* ep         = (const float*)d_in[13];
    float* out = (float*)d_out;

    cudaFuncSetAttribute(fused_kernel,
                         cudaFuncAttributeMaxDynamicSharedMemorySize, SMEM_BYTES);
    fused_kernel<<<NBLK, TPB, SMEM_BYTES>>>(token_ids, resonances, emb_scales,
                                            emb_shifts, emb_norm, frac_norm,
                                            W_enc, b_enc, W_dec, b_dec,
                                            ecc, ep, out);
}

// round 7
// speedup vs baseline: 1.7575x; 1.0015x over previous
#include <cuda_runtime.h>
#include <math.h>

#define B_   2
#define T_   512
#define D_   512
#define NTOK (B_ * T_)       // 1024
#define NBLK 148             // one CTA per SM -> residency guaranteed (148 B300 / 152 GB300)
#define TPB  1024            // 32 warps -> 50% occupancy
#define KMAX 7               // ceil(NTOK / NBLK)
#define KHALF 4              // max tokens per half (ceil(7/2))
#define WT_PITCH 516         // padded pitch (mult of 4 for float4; breaks staging-write conflicts)

// dynamic smem: W_encT [24][516] + emb [KMAX][512]
#define SMEM_BYTES ((24 * WT_PITCH + KMAX * D_) * (int)sizeof(float))

__device__ double   g_blocksum[NBLK];
__device__ unsigned g_bar_cnt;   // zero-init; self-resetting
__device__ unsigned g_bar_gen;   // monotonic across replays

__device__ __forceinline__ void fast_sincos(float x, float* s, float* c) {
    const float INV2PI = 0.15915494309189535f;
    float k = rintf(x * INV2PI);
    float y = fmaf(k, -6.2831855f, x);
    y = fmaf(k, 1.7484556e-7f, y);
    *s = __sinf(y);
    *c = __cosf(y);
}

__device__ __forceinline__ void grid_barrier() {
    __syncthreads();
    if (threadIdx.x == 0) {
        __threadfence();
        unsigned gen = *(volatile unsigned*)&g_bar_gen;
        if (atomicAdd(&g_bar_cnt, 1u) == NBLK - 1) {
            g_bar_cnt = 0;
            __threadfence();
            *(volatile unsigned*)&g_bar_gen = gen + 1;
        } else {
            while (*(volatile unsigned*)&g_bar_gen == gen) { __nanosleep(32); }
        }
        __threadfence();
    }
    __syncthreads();
}

extern __shared__ float s_dyn[];

__global__ __launch_bounds__(TPB, 1) void fused_kernel(
    const int*   __restrict__ token_ids,
    const float* __restrict__ resonances,
    const float* __restrict__ emb_scales,
    const float* __restrict__ emb_shifts,
    const float* __restrict__ emb_norm_p,
    const float* __restrict__ frac_norm_p,
    const float* __restrict__ W_enc,      // [512,24]
    const float* __restrict__ b_enc,      // [24]
    const float* __restrict__ W_dec,      // [24,512]
    const float* __restrict__ b_dec,      // [512]
    const float* __restrict__ ecc_p,
    const float* __restrict__ ep_p,
    float*       __restrict__ out)        // [1024,512]
{
    float* s_wT  = s_dyn;                  // [24][516]
    float* s_emb = s_dyn + 24 * WT_PITCH;  // [KMAX][512]

    __shared__ float  s_redA[KMAX][16];
    __shared__ float  s_proj[KMAX][24];
    __shared__ float  s_latt[KMAX][12];
    __shared__ float  s_corr[KMAX][24];
    __shared__ float  s_f[KMAX], s_ein[KMAX], s_ein2[KMAX], s_scale[KMAX];
    __shared__ float  s_fscale[KMAX];
    __shared__ double s_contrib[KMAX];
    __shared__ float  s_mul;

    const int tid  = threadIdx.x;
    const int lane = tid & 31;
    const int wid  = tid >> 5;
    const int d    = tid & (D_ - 1);   // 0..511
    const int half = tid >> 9;         // 0 or 1
    const int blk  = blockIdx.x;

    const float ecc      = ecc_p[0];
    const float ep       = ep_p[0];
    const float emb_norm = emb_norm_p[0];

    // ---- Phase 0: stage W_enc^T into smem ----
    for (int idx = tid; idx < D_ * 24; idx += TPB) {
        const int dd = idx / 24;
        const int l  = idx - dd * 24;
        s_wT[l * WT_PITCH + dd] = W_enc[idx];
    }

    // ---- Phase A: embeddings; half h handles tokens k = 2*ki + h ----
    const float res_d = resonances[d];
    const float esc_d = emb_scales[d];
    const float esh_d = emb_shifts[d];
    #pragma unroll
    for (int ki = 0; ki < KHALF; ki++) {
        const int k  = 2 * ki + half;
        const int bt = blk + k * NBLK;
        if (k < KMAX && bt < NTOK) {
            const float tv   = (float)(token_ids[bt] % 1000000) * 1e-6f;
            const float base = tv + (float)(bt & (T_ - 1));
            float sn, c;
            fast_sincos(res_d * base, &sn, &c);
            const float e = fmaf(c * (1.f + sn) + sn * sn, esc_d, esh_d);
            s_emb[k * D_ + d] = e;
            float p = e * e;
            #pragma unroll
            for (int o = 16; o; o >>= 1) p += __shfl_xor_sync(0xffffffffu, p, o);
            if (lane == 0) s_redA[k][wid & 15] = p;
        }
    }
    __syncthreads();
    if (wid < KMAX) {
        const int k = wid;
        if (blk + k * NBLK < NTOK) {
            float v = (lane < 16) ? s_redA[k][lane] : 0.f;
            #pragma unroll
            for (int o = 8; o; o >>= 1) v += __shfl_xor_sync(0xffffffffu, v, o);
            if (lane == 0) {
                const float tn = sqrtf(v);
                s_f[k]   = (tn > 0.f) ? (emb_norm / tn) : 1.f;
                s_ein[k] = (tn > 0.f) ? emb_norm : tn;
            }
        }
    }
    __syncthreads();

    // ---- Phase B: proj[k][l] over 32 warps, float4 LDS ----
    const int nk   = (blk + (KMAX - 1) * NBLK < NTOK) ? KMAX : KMAX - 1;
    const int ncol = nk * 24;
    const float4* emb4 = (const float4*)s_emb;
    const float4* wT4  = (const float4*)s_wT;
    for (int c = wid; c < ncol; c += 32) {
        const int k = c / 24;
        const int l = c - k * 24;
        float acc = 0.f;
        #pragma unroll
        for (int j = 0; j < 4; j++) {
            const float4 e4 = emb4[k * (D_ / 4) + lane + 32 * j];
            const float4 w4 = wT4 [l * (WT_PITCH / 4) + lane + 32 * j];
            acc = fmaf(e4.x, w4.x, acc);
            acc = fmaf(e4.y, w4.y, acc);
            acc = fmaf(e4.z, w4.z, acc);
            acc = fmaf(e4.w, w4.w, acc);
        }
        #pragma unroll
        for (int o = 16; o; o >>= 1) acc += __shfl_xor_sync(0xffffffffu, acc, o);
        if (lane == 0) s_proj[k][l] = fmaf(s_f[k], acc, b_enc[l]);
    }
    __syncthreads();

    // ---- Phase B2: Golay pipeline, one warp per token ----
    if (wid < nk) {
        const int k = wid;
        float latt = 0.f;
        if (lane < 12) {
            float ge = s_proj[k][lane];
            #pragma unroll
            for (int j = 0; j < 11; j++)
                if ((lane + j) & 1) ge += s_proj[k][12 + j];
            if (lane & 1) ge += s_proj[k][23];
            latt = rintf(ge / ecc) * ecc;
        }
        float ls = latt * latt;
        #pragma unroll
        for (int o = 16; o; o >>= 1) ls += __shfl_xor_sync(0xffffffffu, ls, o);
        const float e_out  = sqrtf(ls);
        const float lscale = (s_ein[k] / (e_out + 1e-8f)) * ep;
        latt *= lscale;
        if (lane < 12) s_latt[k][lane] = latt;
        __syncwarp();
        if (lane < 24) {
            float gd;
            if (lane < 12) {
                gd = s_latt[k][lane];
            } else if (lane < 23) {
                const int j = lane - 12;
                gd = 0.f;
                #pragma unroll
                for (int kk = 0; kk < 12; kk++)
                    if ((kk + j) & 1) gd += s_latt[k][kk];
            } else {
                gd = s_latt[k][1] + s_latt[k][3] + s_latt[k][5] + s_latt[k][7]
                   + s_latt[k][9] + s_latt[k][11];
            }
            s_corr[k][lane] = (fabsf(gd) > ecc) ? gd : 0.f;
        }
        if (lane == 0) s_ein2[k] = e_out * lscale;
    }
    __syncthreads();

    // ---- Phase C: dec matvec straight from global (single-use data) ----
    float acc[KHALF];
    const float bd = __ldg(&b_dec[d]);
    #pragma unroll
    for (int ki = 0; ki < KHALF; ki++) acc[ki] = bd;
    #pragma unroll
    for (int l = 0; l < 24; l++) {
        const float wl = __ldg(&W_dec[l * D_ + d]);
        #pragma unroll
        for (int ki = 0; ki < KHALF; ki++) {
            const int k = 2 * ki + half;
            if (k < KMAX) acc[ki] = fmaf(s_corr[k][l], wl, acc[ki]);
        }
    }
    #pragma unroll
    for (int ki = 0; ki < KHALF; ki++) {
        const int k = 2 * ki + half;
        if (k < KMAX) {
            float p = acc[ki] * acc[ki];
            #pragma unroll
            for (int o = 16; o; o >>= 1) p += __shfl_xor_sync(0xffffffffu, p, o);
            if (lane == 0) s_redA[k][wid & 15] = p;
        }
    }
    __syncthreads();
    if (wid < KMAX) {
        const int k = wid;
        float v = (lane < 16) ? s_redA[k][lane] : 0.f;
        #pragma unroll
        for (int o = 8; o; o >>= 1) v += __shfl_xor_sync(0xffffffffu, v, o);
        if (lane == 0) {
            if (k < nk) {
                const float e2 = sqrtf(fmaxf(v, 0.f));
                const float sc = s_ein2[k] / (e2 + 1e-8f) * ep;
                s_scale[k] = sc;
                const double tn = (double)(sc * e2);
                s_contrib[k] = tn * tn;
            } else {
                s_contrib[k] = 0.0;
            }
        }
    }
    __syncthreads();
    if (tid == 0) {
        double s = 0.0;
        #pragma unroll
        for (int k = 0; k < KMAX; k++) s += s_contrib[k];
        g_blocksum[blk] = s;
    }

    // ---- Grid barrier (all CTAs resident) ----
    grid_barrier();

    // ---- Deterministic global reduce + fused scaled write from registers ----
    if (wid == 0) {
        double s = 0.0;
        for (int i = lane; i < NBLK; i += 32) s += __ldcg(&g_blocksum[i]);
        #pragma unroll
        for (int o = 16; o; o >>= 1) s += __shfl_xor_sync(0xffffffffu, s, o);
        if (lane == 0) s_mul = frac_norm_p[0] * (float)sqrt(s);
    } else if (wid == 1 && lane < KMAX) {
        // nothing: placeholder to keep warp1 busy-free
    }
    __syncthreads();
    if (tid < KMAX) s_fscale[tid] = s_scale[tid] * s_mul;
    __syncthreads();
    #pragma unroll
    for (int ki = 0; ki < KHALF; ki++) {
        const int k  = 2 * ki + half;
        const int bt = blk + k * NBLK;
        if (k < KMAX && bt < NTOK)
            out[bt * D_ + d] = acc[ki] * s_fscale[k];
    }
}

extern "C" void kernel_launch(void* const* d_in, const int* in_sizes, int n_in,
                              void* d_out, int out_size)
{
    (void)in_sizes; (void)n_in; (void)out_size;
    const int*   token_ids  = (const int*)  d_in[0];
    const float* resonances = (const float*)d_in[1];
    const float* emb_scales = (const float*)d_in[2];
    const float* emb_shifts = (const float*)d_in[3];
    const float* emb_norm   = (const float*)d_in[4];
    // d_in[5] scale_weights, d_in[6] fractal_bias: cancel out of the output exactly
    const float* frac_norm  = (const float*)d_in[7];
    const float* W_enc      = (const float*)d_in[8];
    const float* b_enc      = (const float*)d_in[9];
    const float* W_dec      = (const float*)d_in[10];
    const float* b_dec      = (const float*)d_in[11];
    const float* ecc        = (const float*)d_in[12];
    const float* ep         = (const float*)d_in[13];
    float* out = (float*)d_out;

    cudaFuncSetAttribute(fused_kernel,
                         cudaFuncAttributeMaxDynamicSharedMemorySize, SMEM_BYTES);
    fused_kernel<<<NBLK, TPB, SMEM_BYTES>>>(token_ids, resonances, emb_scales,
                                            emb_shifts, emb_norm, frac_norm,
                                            W_enc, b_enc, W_dec, b_dec,
                                            ecc, ep, out);
}

// round 8
// speedup vs baseline: 2.0121x; 1.1448x over previous
#include <cuda_runtime.h>
#include <math.h>

#define B_   2
#define T_   512
#define D_   512
#define NTOK (B_ * T_)       // 1024
#define NTOT (B_ * T_ * D_)  // 524288

// device scratch (no allocs allowed)
__device__ float4 g_WencT4[24 * (D_ / 4)];   // W_enc^T, [24][512] floats, float4-aligned
__device__ double g_sumsq;

__device__ __forceinline__ void fast_sincos(float x, float* s, float* c) {
    const float INV2PI = 0.15915494309189535f;
    float k = rintf(x * INV2PI);
    float y = fmaf(k, -6.2831855f, x);
    y = fmaf(k, 1.7484556e-7f, y);
    *s = __sinf(y);
    *c = __cosf(y);
}

// ---------------- P: transpose W_enc, zero accumulator (24 x 512) ----------------
__global__ __launch_bounds__(512) void prep_kernel(const float* __restrict__ W_enc)
{
    const int l  = blockIdx.x;    // 0..23
    const int dd = threadIdx.x;   // 0..511
    ((float*)g_WencT4)[l * D_ + dd] = W_enc[dd * 24 + l];   // coalesced write
    if (l == 0 && dd == 0) g_sumsq = 0.0;
}

// ---------------- K1: one token per block (1024 x 256) ----------------
__global__ __launch_bounds__(256) void token_kernel(
    const int*   __restrict__ token_ids,
    const float* __restrict__ resonances,
    const float* __restrict__ emb_scales,
    const float* __restrict__ emb_shifts,
    const float* __restrict__ emb_norm_p,
    const float* __restrict__ b_enc,      // [24]
    const float* __restrict__ W_dec,      // [24,512]
    const float* __restrict__ b_dec,      // [512]
    const float* __restrict__ ecc_p,
    const float* __restrict__ ep_p,
    float*       __restrict__ out)        // [1024,512] <- res * scale_t (pre-global-norm)
{
    __shared__ float4 s_emb4[D_ / 4];
    __shared__ float  s_red[8];
    __shared__ float  s_proj[24];
    __shared__ float  s_latt[12];
    __shared__ float  s_corr[24];
    __shared__ float  s_s[4];            // f, e_in, e_in2, scale

    float* s_emb = (float*)s_emb4;

    const int bt   = blockIdx.x;
    const int tid  = threadIdx.x;
    const int lane = tid & 31;
    const int wid  = tid >> 5;

    const float ecc      = ecc_p[0];
    const float ep       = ep_p[0];
    const float emb_norm = emb_norm_p[0];

    // ---- Phase A: embedding (2 dims/thread) + token norm ----
    const float tv   = (float)(token_ids[bt] % 1000000) * 1e-6f;
    const float base = tv + (float)(bt & (T_ - 1));

    float sn0, c0, sn1, c1;
    fast_sincos(resonances[tid]       * base, &sn0, &c0);
    fast_sincos(resonances[tid + 256] * base, &sn1, &c1);
    const float e0 = fmaf(c0 * (1.f + sn0) + sn0 * sn0, emb_scales[tid],       emb_shifts[tid]);
    const float e1 = fmaf(c1 * (1.f + sn1) + sn1 * sn1, emb_scales[tid + 256], emb_shifts[tid + 256]);
    s_emb[tid]       = e0;
    s_emb[tid + 256] = e1;
    float p = e0 * e0 + e1 * e1;
    #pragma unroll
    for (int o = 16; o; o >>= 1) p += __shfl_xor_sync(0xffffffffu, p, o);
    if (lane == 0) s_red[wid] = p;
    __syncthreads();
    if (tid < 32) {
        float v = (lane < 8) ? s_red[lane] : 0.f;
        #pragma unroll
        for (int o = 4; o; o >>= 1) v += __shfl_xor_sync(0xffffffffu, v, o);
        if (lane == 0) {
            const float tn = sqrtf(v);
            s_s[0] = (tn > 0.f) ? (emb_norm / tn) : 1.f;   // f
            s_s[1] = (tn > 0.f) ? emb_norm : tn;           // e_in
        }
    }
    __syncthreads();
    const float f = s_s[0];

    // ---- Phase B: proj[l] = f*(emb . WencT[l]) + b_enc[l]; 8 warps x 3 cols ----
    #pragma unroll
    for (int c = 0; c < 3; c++) {
        const int l = wid + 8 * c;
        float acc = 0.f;
        #pragma unroll
        for (int j = 0; j < 4; j++) {
            const float4 e4 = s_emb4[lane + 32 * j];
            const float4 w4 = g_WencT4[l * (D_ / 4) + lane + 32 * j];
            acc = fmaf(e4.x, w4.x, acc);
            acc = fmaf(e4.y, w4.y, acc);
            acc = fmaf(e4.z, w4.z, acc);
            acc = fmaf(e4.w, w4.w, acc);
        }
        #pragma unroll
        for (int o = 16; o; o >>= 1) acc += __shfl_xor_sync(0xffffffffu, acc, o);
        if (lane == 0) s_proj[l] = fmaf(f, acc, b_enc[l]);
    }
    __syncthreads();

    // ---- Phase B2: Golay encode/quantize/rescale/decode/threshold (warp 0) ----
    if (wid == 0) {
        const float e_in = s_s[1];
        float latt = 0.f;
        if (lane < 12) {
            float ge = s_proj[lane];
            #pragma unroll
            for (int j = 0; j < 11; j++)
                if ((lane + j) & 1) ge += s_proj[12 + j];
            if (lane & 1) ge += s_proj[23];
            latt = rintf(ge / ecc) * ecc;
        }
        float ls = latt * latt;
        #pragma unroll
        for (int o = 16; o; o >>= 1) ls += __shfl_xor_sync(0xffffffffu, ls, o);
        const float e_out  = sqrtf(ls);
        const float lscale = (e_in / (e_out + 1e-8f)) * ep;
        latt *= lscale;
        if (lane < 12) s_latt[lane] = latt;
        __syncwarp();
        if (lane < 24) {
            float gd;
            if (lane < 12) {
                gd = s_latt[lane];
            } else if (lane < 23) {
                const int j = lane - 12;
                gd = 0.f;
                #pragma unroll
                for (int kk = 0; kk < 12; kk++)
                    if ((kk + j) & 1) gd += s_latt[kk];
            } else {
                gd = s_latt[1] + s_latt[3] + s_latt[5] + s_latt[7] + s_latt[9] + s_latt[11];
            }
            s_corr[lane] = (fabsf(gd) > ecc) ? gd : 0.f;
        }
        if (lane == 0) s_s[2] = e_out * lscale;   // e_in2
    }
    __syncthreads();

    // ---- Phase C: res = corr @ W_dec + b_dec (2 dims/thread, W_dec L1-resident) ----
    float acc0 = __ldg(&b_dec[tid]);
    float acc1 = __ldg(&b_dec[tid + 256]);
    #pragma unroll
    for (int l = 0; l < 24; l++) {
        const float cl = s_corr[l];
        acc0 = fmaf(cl, __ldg(&W_dec[l * D_ + tid]),       acc0);
        acc1 = fmaf(cl, __ldg(&W_dec[l * D_ + tid + 256]), acc1);
    }
    float pr = acc0 * acc0 + acc1 * acc1;
    #pragma unroll
    for (int o = 16; o; o >>= 1) pr += __shfl_xor_sync(0xffffffffu, pr, o);
    if (lane == 0) s_red[wid] = pr;
    __syncthreads();
    if (tid < 32) {
        float v = (lane < 8) ? s_red[lane] : 0.f;
        #pragma unroll
        for (int o = 4; o; o >>= 1) v += __shfl_xor_sync(0xffffffffu, v, o);
        if (lane == 0) {
            const float e2 = sqrtf(fmaxf(v, 0.f));
            const float sc = s_s[2] / (e2 + 1e-8f) * ep;
            s_s[3] = sc;
            const double tn = (double)(sc * e2);
            atomicAdd(&g_sumsq, tn * tn);     // RED.f64, return unused
        }
    }
    __syncthreads();
    const float sc = s_s[3];
    out[bt * D_ + tid]       = acc0 * sc;
    out[bt * D_ + tid + 256] = acc1 * sc;
}

// ---------------- K2: out *= frac_norm * ||res||  (float4 RMW) ----------------
__global__ __launch_bounds__(256) void scale_kernel(
    float4* __restrict__ out4, const float* __restrict__ frac_norm_p)
{
    __shared__ float s_m;
    if (threadIdx.x == 0) s_m = frac_norm_p[0] * (float)sqrt(g_sumsq);
    __syncthreads();
    const float m = s_m;
    const int i = blockIdx.x * blockDim.x + threadIdx.x;   // < NTOT/4
    float4 v = out4[i];
    v.x *= m; v.y *= m; v.z *= m; v.w *= m;
    out4[i] = v;
}

extern "C" void kernel_launch(void* const* d_in, const int* in_sizes, int n_in,
                              void* d_out, int out_size)
{
    (void)in_sizes; (void)n_in; (void)out_size;
    const int*   token_ids  = (const int*)  d_in[0];
    const float* resonances = (const float*)d_in[1];
    const float* emb_scales = (const float*)d_in[2];
    const float* emb_shifts = (const float*)d_in[3];
    const float* emb_norm   = (const float*)d_in[4];
    // d_in[5] scale_weights, d_in[6] fractal_bias: cancel out of the output exactly
    const float* frac_norm  = (const float*)d_in[7];
    const float* W_enc      = (const float*)d_in[8];
    const float* b_enc      = (const float*)d_in[9];
    const float* W_dec      = (const float*)d_in[10];
    const float* b_dec      = (const float*)d_in[11];
    const float* ecc        = (const float*)d_in[12];
    const float* ep         = (const float*)d_in[13];
    float* out = (float*)d_out;

    prep_kernel<<<24, 512>>>(W_enc);
    token_kernel<<<NTOK, 256>>>(token_ids, resonances, emb_scales, emb_shifts,
                                emb_norm, b_enc, W_dec, b_dec, ecc, ep, out);
    scale_kernel<<<NTOT / 4 / 256, 256>>>((float4*)out, frac_norm);
}